// round 7
// baseline (speedup 1.0000x reference)
#include <cuda_runtime.h>
#include <math.h>

#define NSEL 1024
#define DD 32
#define KK 128
#define EPSF 1e-5f
#define PI_HALF_F 1.57079632679489661923f

#define TILE 64
#define LHS 33   // padded row stride for L/H tiles (32 + 1)
#define WS 129   // padded row stride for omega tiles (128 + 1)

// ---- scratch (device globals: no allocation allowed) ----
__device__ float g_L[NSEL * DD];
__device__ float g_H[NSEL * DD];
__device__ float g_ip[NSEL];
__device__ double g_acc[6]; // 0:S_dd 1:S_oo 2:S_do 3:overlap 4:exceed 5:shape

// ---------------------------------------------------------------------------
__global__ void init_kernel() {
    if (threadIdx.x < 6) g_acc[threadIdx.x] = 0.0;
}

// ---------------------------------------------------------------------------
// One block per selected row: gather L/H, compute exceed + shape + ip.
__global__ void gather_kernel(const float* __restrict__ cl, const float* __restrict__ ch,
                              const float* __restrict__ pL, const float* __restrict__ pH,
                              const float* __restrict__ pR, const float* __restrict__ lr,
                              const float* __restrict__ om, const int* __restrict__ idxs) {
    int i = blockIdx.x;
    int tid = threadIdx.x;       // 128 threads
    int id = idxs[i];

    float exc = 0.f, shp = 0.f;
    if (tid < DD) {
        float L = cl[id * DD + tid];
        float H = ch[id * DD + tid];
        g_L[i * DD + tid] = L;
        g_H[i * DD + tid] = H;
        float pl = pL[tid], ph = pH[tid];
        exc = fmaxf(pl - L, 0.f) + fmaxf(H - ph, 0.f)
            + fmaxf(pl - H, 0.f) + fmaxf(L - ph, 0.f);
        float num = fmaxf((H - L) / pR[tid], EPSF);
        float sdiv = num / lr[id];
        sdiv = fminf(fmaxf(sdiv, 0.01f), 1.99f);
        shp = fabsf(tanf((sdiv - 1.0f) * PI_HALF_F));
    }
    float w = om[i * KK + tid];
    float ip = w * w;

#pragma unroll
    for (int off = 16; off > 0; off >>= 1) {
        exc += __shfl_xor_sync(0xffffffffu, exc, off);
        shp += __shfl_xor_sync(0xffffffffu, shp, off);
        ip  += __shfl_xor_sync(0xffffffffu, ip,  off);
    }
    __shared__ float sred[3][4];
    int warp = tid >> 5, lane = tid & 31;
    if (lane == 0) { sred[0][warp] = exc; sred[1][warp] = shp; sred[2][warp] = ip; }
    __syncthreads();
    if (tid == 0) {
        float e = sred[0][0] + sred[0][1] + sred[0][2] + sred[0][3];
        float s = sred[1][0] + sred[1][1] + sred[1][2] + sred[1][3];
        float p = sred[2][0] + sred[2][1] + sred[2][2] + sred[2][3];
        g_ip[i] = p;
        atomicAdd(&g_acc[4], (double)e);
        atomicAdd(&g_acc[5], (double)s);
    }
}

// ---------------------------------------------------------------------------
// Pairwise kernel: 64x64 pair tile per block, 16x16 threads, 4x4 microtile.
// Thread (tx,ty) owns i-rows {ty+16r} and j-rows {tx+16c}: stride-16 row
// assignment + padded smem strides (33/129) => all inner-loop LDS conflict-free.
__global__ void __launch_bounds__(256, 2)
pair_kernel(const float* __restrict__ om) {
    extern __shared__ float sm[];
    float* sLi = sm;
    float* sHi = sLi + TILE * LHS;
    float* sLj = sHi + TILE * LHS;
    float* sHj = sLj + TILE * LHS;
    float* sWi = sHj + TILE * LHS;
    float* sWj = sWi + TILE * WS;

    int tx = threadIdx.x, ty = threadIdx.y;
    int tid = ty * 16 + tx;
    int i0 = blockIdx.y * TILE;
    int j0 = blockIdx.x * TILE;

    // fill L/H tiles
    for (int p = tid; p < TILE * DD; p += 256) {
        int r = p >> 5, d = p & 31;
        sLi[r * LHS + d] = g_L[(i0 + r) * DD + d];
        sHi[r * LHS + d] = g_H[(i0 + r) * DD + d];
        sLj[r * LHS + d] = g_L[(j0 + r) * DD + d];
        sHj[r * LHS + d] = g_H[(j0 + r) * DD + d];
    }
    // fill omega tiles
    for (int p = tid; p < TILE * KK; p += 256) {
        int r = p >> 7, k = p & 127;
        sWi[r * WS + k] = om[(i0 + r) * KK + k];
        sWj[r * WS + k] = om[(j0 + r) * KK + k];
    }
    __syncthreads();

    float dot[4][4], dacc[4][4], ovacc[4][4];
#pragma unroll
    for (int r = 0; r < 4; r++)
#pragma unroll
        for (int c = 0; c < 4; c++) { dot[r][c] = 0.f; dacc[r][c] = 0.f; ovacc[r][c] = 0.f; }

    // embedding dot products
#pragma unroll 4
    for (int k = 0; k < KK; k++) {
        float wi[4], wj[4];
#pragma unroll
        for (int r = 0; r < 4; r++) wi[r] = sWi[(ty + 16 * r) * WS + k];
#pragma unroll
        for (int c = 0; c < 4; c++) wj[c] = sWj[(tx + 16 * c) * WS + k];
#pragma unroll
        for (int r = 0; r < 4; r++)
#pragma unroll
            for (int c = 0; c < 4; c++)
                dot[r][c] = fmaf(wi[r], wj[c], dot[r][c]);
    }

    // box overlap + center distances
#pragma unroll 2
    for (int d = 0; d < DD; d++) {
        float Li[4], Hi[4], Si[4], Lj[4], Hj[4], Sj[4];
#pragma unroll
        for (int r = 0; r < 4; r++) {
            Li[r] = sLi[(ty + 16 * r) * LHS + d];
            Hi[r] = sHi[(ty + 16 * r) * LHS + d];
            Si[r] = Li[r] + Hi[r];
        }
#pragma unroll
        for (int c = 0; c < 4; c++) {
            Lj[c] = sLj[(tx + 16 * c) * LHS + d];
            Hj[c] = sHj[(tx + 16 * c) * LHS + d];
            Sj[c] = Lj[c] + Hj[c];
        }
#pragma unroll
        for (int r = 0; r < 4; r++)
#pragma unroll
            for (int c = 0; c < 4; c++) {
                float mx = fmaxf(Li[r], Lj[c]);
                float mn = fminf(Hi[r], Hj[c]);
                ovacc[r][c] += fmaxf(mn - mx, 0.f);
                float u = Si[r] - Sj[c];           // = 2*(mid_i - mid_j)
                dacc[r][c] = fmaf(u, u, dacc[r][c]);
            }
    }

    float ipi[4], ipj[4];
#pragma unroll
    for (int r = 0; r < 4; r++) ipi[r] = g_ip[i0 + ty + 16 * r];
#pragma unroll
    for (int c = 0; c < 4; c++) ipj[c] = g_ip[j0 + tx + 16 * c];

    float s_dd = 0.f, s_oo = 0.f, s_do = 0.f, s_ov = 0.f;
#pragma unroll
    for (int r = 0; r < 4; r++)
#pragma unroll
        for (int c = 0; c < 4; c++) {
            float d2v = 0.25f * dacc[r][c];
            float oDv = fmaxf(fmaf(-2.f, dot[r][c], ipi[r] + ipj[c]), EPSF);
            s_dd = fmaf(d2v, d2v, s_dd);
            s_oo = fmaf(oDv, oDv, s_oo);
            s_do = fmaf(d2v, oDv, s_do);
            if ((i0 + ty + 16 * r) != (j0 + tx + 16 * c))
                s_ov += ovacc[r][c];
        }

    // block reduction -> double atomics
#pragma unroll
    for (int off = 16; off > 0; off >>= 1) {
        s_dd += __shfl_xor_sync(0xffffffffu, s_dd, off);
        s_oo += __shfl_xor_sync(0xffffffffu, s_oo, off);
        s_do += __shfl_xor_sync(0xffffffffu, s_do, off);
        s_ov += __shfl_xor_sync(0xffffffffu, s_ov, off);
    }
    __shared__ float bred[4][8];
    int warp = tid >> 5, lane = tid & 31;
    if (lane == 0) { bred[0][warp] = s_dd; bred[1][warp] = s_oo; bred[2][warp] = s_do; bred[3][warp] = s_ov; }
    __syncthreads();
    if (tid == 0) {
        float a0 = 0.f, a1 = 0.f, a2 = 0.f, a3 = 0.f;
#pragma unroll
        for (int w = 0; w < 8; w++) {
            a0 += bred[0][w]; a1 += bred[1][w]; a2 += bred[2][w]; a3 += bred[3][w];
        }
        atomicAdd(&g_acc[0], (double)a0);
        atomicAdd(&g_acc[1], (double)a1);
        atomicAdd(&g_acc[2], (double)a2);
        atomicAdd(&g_acc[3], (double)a3);
    }
}

// ---------------------------------------------------------------------------
__global__ void finalize_kernel(float* __restrict__ out) {
    double S_dd = g_acc[0], S_oo = g_acc[1], S_do = g_acc[2];
    double a = sqrt(S_dd), b = sqrt(S_oo);
    double ac = fmax(a, 1e-5), bc = fmax(b, 1e-5);
    double t = S_dd / (ac * ac) + S_oo / (bc * bc) - 2.0 * S_do / (ac * bc);
    if (t < 0.0) t = 0.0;
    double loss = sqrt(t) + g_acc[3] + g_acc[4] + g_acc[5];
    out[0] = (float)loss;
}

// ---------------------------------------------------------------------------
extern "C" void kernel_launch(void* const* d_in, const int* in_sizes, int n_in,
                              void* d_out, int out_size) {
    const float* cl  = (const float*)d_in[0];  // childrenLower  [4096,32]
    const float* ch  = (const float*)d_in[1];  // childrenHigher [4096,32]
    const float* pL  = (const float*)d_in[2];  // parentL_ [32]
    const float* pH  = (const float*)d_in[3];  // parentH_ [32]
    const float* pR  = (const float*)d_in[4];  // parentRange [32]
    const float* lr  = (const float*)d_in[5];  // leavesRatio [4096]
    const float* om  = (const float*)d_in[6];  // omegaEmb [1024,128]
    const int*  idxs = (const int*)d_in[7];    // idIndexes [1024]
    float* out = (float*)d_out;

    const int SMEM = (4 * TILE * LHS + 2 * TILE * WS) * (int)sizeof(float); // 99840 B
    cudaFuncSetAttribute(pair_kernel, cudaFuncAttributeMaxDynamicSharedMemorySize, SMEM);

    init_kernel<<<1, 32>>>();
    gather_kernel<<<NSEL, 128>>>(cl, ch, pL, pH, pR, lr, om, idxs);
    pair_kernel<<<dim3(NSEL / TILE, NSEL / TILE), dim3(16, 16), SMEM>>>(om);
    finalize_kernel<<<1, 1>>>(out);
}

// round 8
// speedup vs baseline: 1.9221x; 1.9221x over previous
#include <cuda_runtime.h>
#include <math.h>

#define NSEL 1024
#define DD 32
#define KK 128
#define EPSF 1e-5f
#define PI_HALF_F 1.57079632679489661923f

#define TILE 64
#define NTB  (NSEL / TILE)            // 16 tiles per side
#define NBLK (NTB * (NTB + 1) / 2)    // 136 triangular blocks
#define LHS 33   // padded row stride for L/H tiles (32 + 1)
#define WS 129   // padded row stride for omega tiles (128 + 1)

// ---- scratch (device globals: zero-initialized at module load) ----
__device__ float g_L[NSEL * DD];
__device__ float g_H[NSEL * DD];
__device__ float g_ip[NSEL];
__device__ double g_acc[6];     // 0:S_dd 1:S_oo 2:S_do 3:overlap 4:exceed 5:shape
__device__ unsigned g_count;    // pair-block completion counter

// ---------------------------------------------------------------------------
// One block per selected row: gather L/H, compute exceed + shape + ip.
__global__ void gather_kernel(const float* __restrict__ cl, const float* __restrict__ ch,
                              const float* __restrict__ pL, const float* __restrict__ pH,
                              const float* __restrict__ pR, const float* __restrict__ lr,
                              const float* __restrict__ om, const int* __restrict__ idxs) {
    int i = blockIdx.x;
    int tid = threadIdx.x;       // 128 threads
    int id = idxs[i];

    float exc = 0.f, shp = 0.f;
    if (tid < DD) {
        float L = cl[id * DD + tid];
        float H = ch[id * DD + tid];
        g_L[i * DD + tid] = L;
        g_H[i * DD + tid] = H;
        float pl = pL[tid], ph = pH[tid];
        exc = fmaxf(pl - L, 0.f) + fmaxf(H - ph, 0.f)
            + fmaxf(pl - H, 0.f) + fmaxf(L - ph, 0.f);
        float num = fmaxf((H - L) / pR[tid], EPSF);
        float sdiv = num / lr[id];
        sdiv = fminf(fmaxf(sdiv, 0.01f), 1.99f);
        shp = fabsf(tanf((sdiv - 1.0f) * PI_HALF_F));
    }
    float w = om[i * KK + tid];
    float ip = w * w;

#pragma unroll
    for (int off = 16; off > 0; off >>= 1) {
        exc += __shfl_xor_sync(0xffffffffu, exc, off);
        shp += __shfl_xor_sync(0xffffffffu, shp, off);
        ip  += __shfl_xor_sync(0xffffffffu, ip,  off);
    }
    __shared__ float sred[3][4];
    int warp = tid >> 5, lane = tid & 31;
    if (lane == 0) { sred[0][warp] = exc; sred[1][warp] = shp; sred[2][warp] = ip; }
    __syncthreads();
    if (tid == 0) {
        float e = sred[0][0] + sred[0][1] + sred[0][2] + sred[0][3];
        float s = sred[1][0] + sred[1][1] + sred[1][2] + sred[1][3];
        float p = sred[2][0] + sred[2][1] + sred[2][2] + sred[2][3];
        g_ip[i] = p;
        atomicAdd(&g_acc[4], (double)e);
        atomicAdd(&g_acc[5], (double)s);
    }
}

// ---------------------------------------------------------------------------
// Pairwise kernel over the UPPER TRIANGLE of 64x64 pair tiles (136 blocks,
// one wave on 148 SMs). Off-diagonal block partials are weighted x2 (all
// pairwise quantities are symmetric). Last block to finish also performs
// the scalar finalize (fused — no separate finalize launch).
__global__ void __launch_bounds__(256, 2)
pair_kernel(const float* __restrict__ om, float* __restrict__ out) {
    extern __shared__ float sm[];
    float* sLi = sm;
    float* sHi = sLi + TILE * LHS;
    float* sLj = sHi + TILE * LHS;
    float* sHj = sLj + TILE * LHS;
    float* sWi = sHj + TILE * LHS;
    float* sWj = sWi + TILE * WS;

    int tx = threadIdx.x, ty = threadIdx.y;
    int tid = ty * 16 + tx;

    // decode triangular block index -> (by, bx) with by <= bx
    int t = blockIdx.x;
    int by = 0;
    while (t >= NTB - by) { t -= NTB - by; by++; }
    int bx = by + t;
    int i0 = by * TILE;
    int j0 = bx * TILE;

    // fill L/H tiles
    for (int p = tid; p < TILE * DD; p += 256) {
        int r = p >> 5, d = p & 31;
        sLi[r * LHS + d] = g_L[(i0 + r) * DD + d];
        sHi[r * LHS + d] = g_H[(i0 + r) * DD + d];
        sLj[r * LHS + d] = g_L[(j0 + r) * DD + d];
        sHj[r * LHS + d] = g_H[(j0 + r) * DD + d];
    }
    // fill omega tiles
    for (int p = tid; p < TILE * KK; p += 256) {
        int r = p >> 7, k = p & 127;
        sWi[r * WS + k] = om[(i0 + r) * KK + k];
        sWj[r * WS + k] = om[(j0 + r) * KK + k];
    }
    __syncthreads();

    float dot[4][4], dacc[4][4], ovacc[4][4];
#pragma unroll
    for (int r = 0; r < 4; r++)
#pragma unroll
        for (int c = 0; c < 4; c++) { dot[r][c] = 0.f; dacc[r][c] = 0.f; ovacc[r][c] = 0.f; }

    // embedding dot products
#pragma unroll 4
    for (int k = 0; k < KK; k++) {
        float wi[4], wj[4];
#pragma unroll
        for (int r = 0; r < 4; r++) wi[r] = sWi[(ty + 16 * r) * WS + k];
#pragma unroll
        for (int c = 0; c < 4; c++) wj[c] = sWj[(tx + 16 * c) * WS + k];
#pragma unroll
        for (int r = 0; r < 4; r++)
#pragma unroll
            for (int c = 0; c < 4; c++)
                dot[r][c] = fmaf(wi[r], wj[c], dot[r][c]);
    }

    // box overlap + center distances
#pragma unroll 2
    for (int d = 0; d < DD; d++) {
        float Li[4], Hi[4], Si[4], Lj[4], Hj[4], Sj[4];
#pragma unroll
        for (int r = 0; r < 4; r++) {
            Li[r] = sLi[(ty + 16 * r) * LHS + d];
            Hi[r] = sHi[(ty + 16 * r) * LHS + d];
            Si[r] = Li[r] + Hi[r];
        }
#pragma unroll
        for (int c = 0; c < 4; c++) {
            Lj[c] = sLj[(tx + 16 * c) * LHS + d];
            Hj[c] = sHj[(tx + 16 * c) * LHS + d];
            Sj[c] = Lj[c] + Hj[c];
        }
#pragma unroll
        for (int r = 0; r < 4; r++)
#pragma unroll
            for (int c = 0; c < 4; c++) {
                float mx = fmaxf(Li[r], Lj[c]);
                float mn = fminf(Hi[r], Hj[c]);
                ovacc[r][c] += fmaxf(mn - mx, 0.f);
                float u = Si[r] - Sj[c];           // = 2*(mid_i - mid_j)
                dacc[r][c] = fmaf(u, u, dacc[r][c]);
            }
    }

    float ipi[4], ipj[4];
#pragma unroll
    for (int r = 0; r < 4; r++) ipi[r] = g_ip[i0 + ty + 16 * r];
#pragma unroll
    for (int c = 0; c < 4; c++) ipj[c] = g_ip[j0 + tx + 16 * c];

    float s_dd = 0.f, s_oo = 0.f, s_do = 0.f, s_ov = 0.f;
#pragma unroll
    for (int r = 0; r < 4; r++)
#pragma unroll
        for (int c = 0; c < 4; c++) {
            float d2v = 0.25f * dacc[r][c];
            float oDv = fmaxf(fmaf(-2.f, dot[r][c], ipi[r] + ipj[c]), EPSF);
            s_dd = fmaf(d2v, d2v, s_dd);
            s_oo = fmaf(oDv, oDv, s_oo);
            s_do = fmaf(d2v, oDv, s_do);
            if ((i0 + ty + 16 * r) != (j0 + tx + 16 * c))
                s_ov += ovacc[r][c];
        }

    // block reduction -> weighted double atomics
#pragma unroll
    for (int off = 16; off > 0; off >>= 1) {
        s_dd += __shfl_xor_sync(0xffffffffu, s_dd, off);
        s_oo += __shfl_xor_sync(0xffffffffu, s_oo, off);
        s_do += __shfl_xor_sync(0xffffffffu, s_do, off);
        s_ov += __shfl_xor_sync(0xffffffffu, s_ov, off);
    }
    __shared__ float bred[4][8];
    int warp = tid >> 5, lane = tid & 31;
    if (lane == 0) { bred[0][warp] = s_dd; bred[1][warp] = s_oo; bred[2][warp] = s_do; bred[3][warp] = s_ov; }
    __syncthreads();
    if (tid == 0) {
        float a0 = 0.f, a1 = 0.f, a2 = 0.f, a3 = 0.f;
#pragma unroll
        for (int w = 0; w < 8; w++) {
            a0 += bred[0][w]; a1 += bred[1][w]; a2 += bred[2][w]; a3 += bred[3][w];
        }
        double wgt = (by == bx) ? 1.0 : 2.0;   // symmetry: off-diagonal tiles count twice
        atomicAdd(&g_acc[0], wgt * (double)a0);
        atomicAdd(&g_acc[1], wgt * (double)a1);
        atomicAdd(&g_acc[2], wgt * (double)a2);
        atomicAdd(&g_acc[3], wgt * (double)a3);

        __threadfence();
        unsigned prev = atomicAdd(&g_count, 1u);
        if (prev == NBLK - 1) {
            // fused finalize: all pair blocks (and gather, by stream order) done
            __threadfence();
            double S_dd = g_acc[0], S_oo = g_acc[1], S_do = g_acc[2];
            double a = sqrt(S_dd), b = sqrt(S_oo);
            double ac = fmax(a, 1e-5), bc = fmax(b, 1e-5);
            double q = S_dd / (ac * ac) + S_oo / (bc * bc) - 2.0 * S_do / (ac * bc);
            if (q < 0.0) q = 0.0;
            out[0] = (float)(sqrt(q) + g_acc[3] + g_acc[4] + g_acc[5]);
            // reset state for the next graph replay
            g_acc[0] = 0.0; g_acc[1] = 0.0; g_acc[2] = 0.0;
            g_acc[3] = 0.0; g_acc[4] = 0.0; g_acc[5] = 0.0;
            g_count = 0u;
        }
    }
}

// ---------------------------------------------------------------------------
extern "C" void kernel_launch(void* const* d_in, const int* in_sizes, int n_in,
                              void* d_out, int out_size) {
    const float* cl  = (const float*)d_in[0];  // childrenLower  [4096,32]
    const float* ch  = (const float*)d_in[1];  // childrenHigher [4096,32]
    const float* pL  = (const float*)d_in[2];  // parentL_ [32]
    const float* pH  = (const float*)d_in[3];  // parentH_ [32]
    const float* pR  = (const float*)d_in[4];  // parentRange [32]
    const float* lr  = (const float*)d_in[5];  // leavesRatio [4096]
    const float* om  = (const float*)d_in[6];  // omegaEmb [1024,128]
    const int*  idxs = (const int*)d_in[7];    // idIndexes [1024]
    float* out = (float*)d_out;

    const int SMEM = (4 * TILE * LHS + 2 * TILE * WS) * (int)sizeof(float); // 99840 B
    cudaFuncSetAttribute(pair_kernel, cudaFuncAttributeMaxDynamicSharedMemorySize, SMEM);

    gather_kernel<<<NSEL, 128>>>(cl, ch, pL, pH, pR, lr, om, idxs);
    pair_kernel<<<NBLK, dim3(16, 16), SMEM>>>(om, out);
}

// round 9
// speedup vs baseline: 2.0455x; 1.0642x over previous
#include <cuda_runtime.h>
#include <math.h>

#define NSEL 1024
#define DD 32
#define KK 128
#define EPSF 1e-5f
#define PI_HALF_F 1.57079632679489661923f

#define TILE 64
#define NTB  (NSEL / TILE)            // 16 tiles per side
#define NBLK (NTB * (NTB + 1) / 2)    // 136 triangular blocks (one wave)
#define LHS4 36   // padded row stride for L/H tiles (32 + 4) -> 16B aligned rows
#define WS4  132  // padded row stride for omega tiles (128 + 4) -> 16B aligned rows

// ---- global accumulators (zero-initialized at module load; reset each call) ----
__device__ double g_acc[6];     // 0:S_dd 1:S_oo 2:S_do 3:overlap 4:exceed 5:shape
__device__ unsigned g_count;

// ---------------------------------------------------------------------------
// Single fused kernel: 136 triangular 64x64 pair tiles, 256 threads, 4x4
// microtile. Each block gathers its own box rows; diagonal blocks also compute
// exceed+shape; ip computed from the omega tiles in smem. Last block finalizes.
__global__ void __launch_bounds__(256)
pair_kernel(const float* __restrict__ cl, const float* __restrict__ ch,
            const float* __restrict__ pL, const float* __restrict__ pH,
            const float* __restrict__ pR, const float* __restrict__ lr,
            const float* __restrict__ om, const int* __restrict__ idxs,
            float* __restrict__ out) {
    extern __shared__ float sm[];
    float* sLi = sm;
    float* sHi = sLi + TILE * LHS4;
    float* sLj = sHi + TILE * LHS4;
    float* sHj = sLj + TILE * LHS4;
    float* sWi = sHj + TILE * LHS4;
    float* sWj = sWi + TILE * WS4;
    __shared__ float sIpI[TILE], sIpJ[TILE];
    __shared__ float bred[6][8];

    int tx = threadIdx.x, ty = threadIdx.y;
    int tid = ty * 16 + tx;

    // decode triangular block index -> (by, bx) with by <= bx
    int t = blockIdx.x;
    int by = 0;
    while (t >= NTB - by) { t -= NTB - by; by++; }
    int bx = by + t;
    int i0 = by * TILE;
    int j0 = bx * TILE;
    bool diag = (by == bx);

    // ---- gather L/H tiles (vectorized: one float4 row-chunk per slot) ----
    for (int p = tid; p < TILE * (DD / 4); p += 256) {     // 512 slots
        int r = p >> 3, dq = p & 7;
        int gi = idxs[i0 + r];
        int gj = idxs[j0 + r];
        ((float4*)&sLi[r * LHS4])[dq] = ((const float4*)cl)[gi * 8 + dq];
        ((float4*)&sHi[r * LHS4])[dq] = ((const float4*)ch)[gi * 8 + dq];
        ((float4*)&sLj[r * LHS4])[dq] = ((const float4*)cl)[gj * 8 + dq];
        ((float4*)&sHj[r * LHS4])[dq] = ((const float4*)ch)[gj * 8 + dq];
    }
    // ---- omega tiles (coalesced float4) ----
    for (int p = tid; p < TILE * (KK / 4); p += 256) {     // 2048 slots
        int r = p >> 5, kq = p & 31;
        ((float4*)&sWi[r * WS4])[kq] = ((const float4*)om)[(i0 + r) * 32 + kq];
        ((float4*)&sWj[r * WS4])[kq] = ((const float4*)om)[(j0 + r) * 32 + kq];
    }
    __syncthreads();

    // ---- per-row ip = sum(w*w) from smem tiles (4 threads per row) ----
    {
        int row = tid >> 2, q = tid & 3;
        const float4* wi = (const float4*)&sWi[row * WS4 + q * 32];
        const float4* wj = (const float4*)&sWj[row * WS4 + q * 32];
        float pi = 0.f, pj = 0.f;
#pragma unroll
        for (int k = 0; k < 8; k++) {
            float4 a = wi[k], b = wj[k];
            pi = fmaf(a.x, a.x, fmaf(a.y, a.y, fmaf(a.z, a.z, fmaf(a.w, a.w, pi))));
            pj = fmaf(b.x, b.x, fmaf(b.y, b.y, fmaf(b.z, b.z, fmaf(b.w, b.w, pj))));
        }
        pi += __shfl_xor_sync(0xffffffffu, pi, 1);
        pi += __shfl_xor_sync(0xffffffffu, pi, 2);
        pj += __shfl_xor_sync(0xffffffffu, pj, 1);
        pj += __shfl_xor_sync(0xffffffffu, pj, 2);
        if (q == 0) { sIpI[row] = pi; sIpJ[row] = pj; }
    }

    // ---- exceed + shape: computed once per row-tile, by diagonal blocks ----
    float exc = 0.f, shp = 0.f;
    if (diag) {
        for (int p = tid; p < TILE * DD; p += 256) {
            int r = p >> 5, d = p & 31;
            float L = sLi[r * LHS4 + d];
            float H = sHi[r * LHS4 + d];
            float pl = pL[d], ph = pH[d];
            exc += fmaxf(pl - L, 0.f) + fmaxf(H - ph, 0.f)
                 + fmaxf(pl - H, 0.f) + fmaxf(L - ph, 0.f);
            float num = fmaxf((H - L) / pR[d], EPSF);
            float sdiv = num / lr[idxs[i0 + r]];
            sdiv = fminf(fmaxf(sdiv, 0.01f), 1.99f);
            shp += fabsf(tanf((sdiv - 1.0f) * PI_HALF_F));
        }
    }
    __syncthreads();

    float dot[4][4], dacc[4][4], ovacc[4][4];
#pragma unroll
    for (int r = 0; r < 4; r++)
#pragma unroll
        for (int c = 0; c < 4; c++) { dot[r][c] = 0.f; dacc[r][c] = 0.f; ovacc[r][c] = 0.f; }

    // ---- embedding dot products (vectorized k-chunks of 4) ----
    for (int k = 0; k < KK; k += 4) {
        float4 wi[4], wj[4];
#pragma unroll
        for (int r = 0; r < 4; r++) wi[r] = *(const float4*)&sWi[(ty + 16 * r) * WS4 + k];
#pragma unroll
        for (int c = 0; c < 4; c++) wj[c] = *(const float4*)&sWj[(tx + 16 * c) * WS4 + k];
#pragma unroll
        for (int r = 0; r < 4; r++)
#pragma unroll
            for (int c = 0; c < 4; c++) {
                float s = fmaf(wi[r].x, wj[c].x, dot[r][c]);
                s = fmaf(wi[r].y, wj[c].y, s);
                s = fmaf(wi[r].z, wj[c].z, s);
                dot[r][c] = fmaf(wi[r].w, wj[c].w, s);
            }
    }

    // ---- box overlap + center distances (vectorized d-chunks of 4) ----
    for (int d = 0; d < DD; d += 4) {
        float4 Li[4], Hi[4], Si[4], Lj[4], Hj[4], Sj[4];
#pragma unroll
        for (int r = 0; r < 4; r++) {
            Li[r] = *(const float4*)&sLi[(ty + 16 * r) * LHS4 + d];
            Hi[r] = *(const float4*)&sHi[(ty + 16 * r) * LHS4 + d];
            Si[r].x = Li[r].x + Hi[r].x; Si[r].y = Li[r].y + Hi[r].y;
            Si[r].z = Li[r].z + Hi[r].z; Si[r].w = Li[r].w + Hi[r].w;
        }
#pragma unroll
        for (int c = 0; c < 4; c++) {
            Lj[c] = *(const float4*)&sLj[(tx + 16 * c) * LHS4 + d];
            Hj[c] = *(const float4*)&sHj[(tx + 16 * c) * LHS4 + d];
            Sj[c].x = Lj[c].x + Hj[c].x; Sj[c].y = Lj[c].y + Hj[c].y;
            Sj[c].z = Lj[c].z + Hj[c].z; Sj[c].w = Lj[c].w + Hj[c].w;
        }
#pragma unroll
        for (int r = 0; r < 4; r++)
#pragma unroll
            for (int c = 0; c < 4; c++) {
                float u;
                ovacc[r][c] += fmaxf(fminf(Hi[r].x, Hj[c].x) - fmaxf(Li[r].x, Lj[c].x), 0.f);
                u = Si[r].x - Sj[c].x; dacc[r][c] = fmaf(u, u, dacc[r][c]);
                ovacc[r][c] += fmaxf(fminf(Hi[r].y, Hj[c].y) - fmaxf(Li[r].y, Lj[c].y), 0.f);
                u = Si[r].y - Sj[c].y; dacc[r][c] = fmaf(u, u, dacc[r][c]);
                ovacc[r][c] += fmaxf(fminf(Hi[r].z, Hj[c].z) - fmaxf(Li[r].z, Lj[c].z), 0.f);
                u = Si[r].z - Sj[c].z; dacc[r][c] = fmaf(u, u, dacc[r][c]);
                ovacc[r][c] += fmaxf(fminf(Hi[r].w, Hj[c].w) - fmaxf(Li[r].w, Lj[c].w), 0.f);
                u = Si[r].w - Sj[c].w; dacc[r][c] = fmaf(u, u, dacc[r][c]);
            }
    }

    // ---- combine microtile into four scalar partials ----
    float ipi[4], ipj[4];
#pragma unroll
    for (int r = 0; r < 4; r++) ipi[r] = sIpI[ty + 16 * r];
#pragma unroll
    for (int c = 0; c < 4; c++) ipj[c] = sIpJ[tx + 16 * c];

    float s_dd = 0.f, s_oo = 0.f, s_do = 0.f, s_ov = 0.f;
#pragma unroll
    for (int r = 0; r < 4; r++)
#pragma unroll
        for (int c = 0; c < 4; c++) {
            float d2v = 0.25f * dacc[r][c];
            float oDv = fmaxf(fmaf(-2.f, dot[r][c], ipi[r] + ipj[c]), EPSF);
            s_dd = fmaf(d2v, d2v, s_dd);
            s_oo = fmaf(oDv, oDv, s_oo);
            s_do = fmaf(d2v, oDv, s_do);
            if ((i0 + ty + 16 * r) != (j0 + tx + 16 * c))
                s_ov += ovacc[r][c];
        }

    // ---- block reduction ----
#pragma unroll
    for (int off = 16; off > 0; off >>= 1) {
        s_dd += __shfl_xor_sync(0xffffffffu, s_dd, off);
        s_oo += __shfl_xor_sync(0xffffffffu, s_oo, off);
        s_do += __shfl_xor_sync(0xffffffffu, s_do, off);
        s_ov += __shfl_xor_sync(0xffffffffu, s_ov, off);
        exc  += __shfl_xor_sync(0xffffffffu, exc,  off);
        shp  += __shfl_xor_sync(0xffffffffu, shp,  off);
    }
    int warp = tid >> 5, lane = tid & 31;
    if (lane == 0) {
        bred[0][warp] = s_dd; bred[1][warp] = s_oo; bred[2][warp] = s_do;
        bred[3][warp] = s_ov; bred[4][warp] = exc;  bred[5][warp] = shp;
    }
    __syncthreads();
    if (tid == 0) {
        float a0 = 0.f, a1 = 0.f, a2 = 0.f, a3 = 0.f, a4 = 0.f, a5 = 0.f;
#pragma unroll
        for (int w = 0; w < 8; w++) {
            a0 += bred[0][w]; a1 += bred[1][w]; a2 += bred[2][w];
            a3 += bred[3][w]; a4 += bred[4][w]; a5 += bred[5][w];
        }
        double wgt = diag ? 1.0 : 2.0;   // symmetry: off-diagonal tiles count twice
        atomicAdd(&g_acc[0], wgt * (double)a0);
        atomicAdd(&g_acc[1], wgt * (double)a1);
        atomicAdd(&g_acc[2], wgt * (double)a2);
        atomicAdd(&g_acc[3], wgt * (double)a3);
        if (diag) {
            atomicAdd(&g_acc[4], (double)a4);
            atomicAdd(&g_acc[5], (double)a5);
        }

        __threadfence();
        unsigned prev = atomicAdd(&g_count, 1u);
        if (prev == NBLK - 1) {
            __threadfence();
            double S_dd = g_acc[0], S_oo = g_acc[1], S_do = g_acc[2];
            double a = sqrt(S_dd), b = sqrt(S_oo);
            double ac = fmax(a, 1e-5), bc = fmax(b, 1e-5);
            double q = S_dd / (ac * ac) + S_oo / (bc * bc) - 2.0 * S_do / (ac * bc);
            if (q < 0.0) q = 0.0;
            out[0] = (float)(sqrt(q) + g_acc[3] + g_acc[4] + g_acc[5]);
            // reset state for the next graph replay
            g_acc[0] = 0.0; g_acc[1] = 0.0; g_acc[2] = 0.0;
            g_acc[3] = 0.0; g_acc[4] = 0.0; g_acc[5] = 0.0;
            g_count = 0u;
        }
    }
}

// ---------------------------------------------------------------------------
extern "C" void kernel_launch(void* const* d_in, const int* in_sizes, int n_in,
                              void* d_out, int out_size) {
    const float* cl  = (const float*)d_in[0];  // childrenLower  [4096,32]
    const float* ch  = (const float*)d_in[1];  // childrenHigher [4096,32]
    const float* pL  = (const float*)d_in[2];  // parentL_ [32]
    const float* pH  = (const float*)d_in[3];  // parentH_ [32]
    const float* pR  = (const float*)d_in[4];  // parentRange [32]
    const float* lr  = (const float*)d_in[5];  // leavesRatio [4096]
    const float* om  = (const float*)d_in[6];  // omegaEmb [1024,128]
    const int*  idxs = (const int*)d_in[7];    // idIndexes [1024]
    float* out = (float*)d_out;

    const int SMEM = (4 * TILE * LHS4 + 2 * TILE * WS4) * (int)sizeof(float); // 104448 B
    cudaFuncSetAttribute(pair_kernel, cudaFuncAttributeMaxDynamicSharedMemorySize, SMEM);

    pair_kernel<<<NBLK, dim3(16, 16), SMEM>>>(cl, ch, pL, pH, pR, lr, om, idxs, out);
}

// round 10
// speedup vs baseline: 2.2106x; 1.0807x over previous
#include <cuda_runtime.h>
#include <math.h>

#define NSEL 1024
#define DD 32
#define KK 128
#define EPSF 1e-5f
#define PI_HALF_F 1.57079632679489661923f

#define TILE 64
#define NTB  (NSEL / TILE)            // 16 tiles per side
#define NBLK (NTB * (NTB + 1) / 2)    // 136 triangular blocks (one wave)
#define NTHR 512
#define LHS4 36   // padded row stride for L/H tiles (32 + 4) -> 16B aligned
#define WS4  132  // padded row stride for omega tiles (128 + 4) -> 16B aligned

// ---- global accumulators (zero-initialized at module load; reset each call) ----
__device__ double g_acc[6];     // 0:S_dd 1:S_oo 2:S_do 3:overlap 4:exceed 5:shape
__device__ unsigned g_count;

// ---------------------------------------------------------------------------
// Single fused kernel: 136 triangular 64x64 pair tiles, 512 threads (16 warps
// -> 4 per SMSP for latency hiding), 2x4 microtile per thread.
// Diagonal blocks also compute exceed+shape; last block finalizes.
__global__ void __launch_bounds__(NTHR)
pair_kernel(const float* __restrict__ cl, const float* __restrict__ ch,
            const float* __restrict__ pL, const float* __restrict__ pH,
            const float* __restrict__ pR, const float* __restrict__ lr,
            const float* __restrict__ om, const int* __restrict__ idxs,
            float* __restrict__ out) {
    extern __shared__ float sm[];
    float* sLi = sm;
    float* sHi = sLi + TILE * LHS4;
    float* sLj = sHi + TILE * LHS4;
    float* sHj = sLj + TILE * LHS4;
    float* sWi = sHj + TILE * LHS4;
    float* sWj = sWi + TILE * WS4;
    __shared__ float sIpI[TILE], sIpJ[TILE];
    __shared__ float bred[6][16];

    int tx = threadIdx.x, ty = threadIdx.y;      // (16, 32)
    int tid = ty * 16 + tx;

    // decode triangular block index -> (by, bx) with by <= bx
    int t = blockIdx.x;
    int by = 0;
    while (t >= NTB - by) { t -= NTB - by; by++; }
    int bx = by + t;
    int i0 = by * TILE;
    int j0 = bx * TILE;
    bool diag = (by == bx);

    // ---- gather L/H tiles (float4 row-chunks) ----
    for (int p = tid; p < TILE * (DD / 4); p += NTHR) {    // 512 slots
        int r = p >> 3, dq = p & 7;
        int gi = idxs[i0 + r];
        int gj = idxs[j0 + r];
        ((float4*)&sLi[r * LHS4])[dq] = ((const float4*)cl)[gi * 8 + dq];
        ((float4*)&sHi[r * LHS4])[dq] = ((const float4*)ch)[gi * 8 + dq];
        ((float4*)&sLj[r * LHS4])[dq] = ((const float4*)cl)[gj * 8 + dq];
        ((float4*)&sHj[r * LHS4])[dq] = ((const float4*)ch)[gj * 8 + dq];
    }
    // ---- omega tiles (coalesced float4) ----
    for (int p = tid; p < TILE * (KK / 4); p += NTHR) {    // 2048 slots
        int r = p >> 5, kq = p & 31;
        ((float4*)&sWi[r * WS4])[kq] = ((const float4*)om)[(i0 + r) * 32 + kq];
        ((float4*)&sWj[r * WS4])[kq] = ((const float4*)om)[(j0 + r) * 32 + kq];
    }
    __syncthreads();

    // ---- per-row ip = sum(w*w): 8 threads per row, 16 floats each ----
    {
        int row = tid >> 3, q = tid & 7;
        const float4* wi = (const float4*)&sWi[row * WS4 + q * 16];
        const float4* wj = (const float4*)&sWj[row * WS4 + q * 16];
        float pi = 0.f, pj = 0.f;
#pragma unroll
        for (int k = 0; k < 4; k++) {
            float4 a = wi[k], b = wj[k];
            pi = fmaf(a.x, a.x, fmaf(a.y, a.y, fmaf(a.z, a.z, fmaf(a.w, a.w, pi))));
            pj = fmaf(b.x, b.x, fmaf(b.y, b.y, fmaf(b.z, b.z, fmaf(b.w, b.w, pj))));
        }
#pragma unroll
        for (int off = 1; off < 8; off <<= 1) {
            pi += __shfl_xor_sync(0xffffffffu, pi, off);
            pj += __shfl_xor_sync(0xffffffffu, pj, off);
        }
        if (q == 0) { sIpI[row] = pi; sIpJ[row] = pj; }
    }

    // ---- exceed + shape: computed once per row-tile, by diagonal blocks ----
    float exc = 0.f, shp = 0.f;
    if (diag) {
        for (int p = tid; p < TILE * DD; p += NTHR) {
            int r = p >> 5, d = p & 31;
            float L = sLi[r * LHS4 + d];
            float H = sHi[r * LHS4 + d];
            float pl = pL[d], ph = pH[d];
            exc += fmaxf(pl - L, 0.f) + fmaxf(H - ph, 0.f)
                 + fmaxf(pl - H, 0.f) + fmaxf(L - ph, 0.f);
            float num = fmaxf((H - L) / pR[d], EPSF);
            float sdiv = num / lr[idxs[i0 + r]];
            sdiv = fminf(fmaxf(sdiv, 0.01f), 1.99f);
            shp += fabsf(tanf((sdiv - 1.0f) * PI_HALF_F));
        }
    }
    __syncthreads();

    // microtile: i-rows {ty, ty+32}, j-cols {tx + 16c, c<4}
    float dot[2][4], dacc[2][4], ovacc[2][4];
#pragma unroll
    for (int r = 0; r < 2; r++)
#pragma unroll
        for (int c = 0; c < 4; c++) { dot[r][c] = 0.f; dacc[r][c] = 0.f; ovacc[r][c] = 0.f; }

    // ---- embedding dot products (k-chunks of 4) ----
    for (int k = 0; k < KK; k += 4) {
        float4 wi[2], wj[4];
#pragma unroll
        for (int r = 0; r < 2; r++) wi[r] = *(const float4*)&sWi[(ty + 32 * r) * WS4 + k];
#pragma unroll
        for (int c = 0; c < 4; c++) wj[c] = *(const float4*)&sWj[(tx + 16 * c) * WS4 + k];
#pragma unroll
        for (int r = 0; r < 2; r++)
#pragma unroll
            for (int c = 0; c < 4; c++) {
                float s = fmaf(wi[r].x, wj[c].x, dot[r][c]);
                s = fmaf(wi[r].y, wj[c].y, s);
                s = fmaf(wi[r].z, wj[c].z, s);
                dot[r][c] = fmaf(wi[r].w, wj[c].w, s);
            }
    }

    // ---- box overlap + center distances (d-chunks of 4) ----
    for (int d = 0; d < DD; d += 4) {
        float4 Li[2], Hi[2], Si[2], Lj[4], Hj[4], Sj[4];
#pragma unroll
        for (int r = 0; r < 2; r++) {
            Li[r] = *(const float4*)&sLi[(ty + 32 * r) * LHS4 + d];
            Hi[r] = *(const float4*)&sHi[(ty + 32 * r) * LHS4 + d];
            Si[r].x = Li[r].x + Hi[r].x; Si[r].y = Li[r].y + Hi[r].y;
            Si[r].z = Li[r].z + Hi[r].z; Si[r].w = Li[r].w + Hi[r].w;
        }
#pragma unroll
        for (int c = 0; c < 4; c++) {
            Lj[c] = *(const float4*)&sLj[(tx + 16 * c) * LHS4 + d];
            Hj[c] = *(const float4*)&sHj[(tx + 16 * c) * LHS4 + d];
            Sj[c].x = Lj[c].x + Hj[c].x; Sj[c].y = Lj[c].y + Hj[c].y;
            Sj[c].z = Lj[c].z + Hj[c].z; Sj[c].w = Lj[c].w + Hj[c].w;
        }
#pragma unroll
        for (int r = 0; r < 2; r++)
#pragma unroll
            for (int c = 0; c < 4; c++) {
                float u;
                ovacc[r][c] += fmaxf(fminf(Hi[r].x, Hj[c].x) - fmaxf(Li[r].x, Lj[c].x), 0.f);
                u = Si[r].x - Sj[c].x; dacc[r][c] = fmaf(u, u, dacc[r][c]);
                ovacc[r][c] += fmaxf(fminf(Hi[r].y, Hj[c].y) - fmaxf(Li[r].y, Lj[c].y), 0.f);
                u = Si[r].y - Sj[c].y; dacc[r][c] = fmaf(u, u, dacc[r][c]);
                ovacc[r][c] += fmaxf(fminf(Hi[r].z, Hj[c].z) - fmaxf(Li[r].z, Lj[c].z), 0.f);
                u = Si[r].z - Sj[c].z; dacc[r][c] = fmaf(u, u, dacc[r][c]);
                ovacc[r][c] += fmaxf(fminf(Hi[r].w, Hj[c].w) - fmaxf(Li[r].w, Lj[c].w), 0.f);
                u = Si[r].w - Sj[c].w; dacc[r][c] = fmaf(u, u, dacc[r][c]);
            }
    }

    // ---- combine microtile into scalar partials ----
    float ipi[2], ipj[4];
#pragma unroll
    for (int r = 0; r < 2; r++) ipi[r] = sIpI[ty + 32 * r];
#pragma unroll
    for (int c = 0; c < 4; c++) ipj[c] = sIpJ[tx + 16 * c];

    float s_dd = 0.f, s_oo = 0.f, s_do = 0.f, s_ov = 0.f;
#pragma unroll
    for (int r = 0; r < 2; r++)
#pragma unroll
        for (int c = 0; c < 4; c++) {
            float d2v = 0.25f * dacc[r][c];
            float oDv = fmaxf(fmaf(-2.f, dot[r][c], ipi[r] + ipj[c]), EPSF);
            s_dd = fmaf(d2v, d2v, s_dd);
            s_oo = fmaf(oDv, oDv, s_oo);
            s_do = fmaf(d2v, oDv, s_do);
            if ((i0 + ty + 32 * r) != (j0 + tx + 16 * c))
                s_ov += ovacc[r][c];
        }

    // ---- block reduction ----
#pragma unroll
    for (int off = 16; off > 0; off >>= 1) {
        s_dd += __shfl_xor_sync(0xffffffffu, s_dd, off);
        s_oo += __shfl_xor_sync(0xffffffffu, s_oo, off);
        s_do += __shfl_xor_sync(0xffffffffu, s_do, off);
        s_ov += __shfl_xor_sync(0xffffffffu, s_ov, off);
        exc  += __shfl_xor_sync(0xffffffffu, exc,  off);
        shp  += __shfl_xor_sync(0xffffffffu, shp,  off);
    }
    int warp = tid >> 5, lane = tid & 31;
    if (lane == 0) {
        bred[0][warp] = s_dd; bred[1][warp] = s_oo; bred[2][warp] = s_do;
        bred[3][warp] = s_ov; bred[4][warp] = exc;  bred[5][warp] = shp;
    }
    __syncthreads();
    if (tid == 0) {
        float a0 = 0.f, a1 = 0.f, a2 = 0.f, a3 = 0.f, a4 = 0.f, a5 = 0.f;
#pragma unroll
        for (int w = 0; w < 16; w++) {
            a0 += bred[0][w]; a1 += bred[1][w]; a2 += bred[2][w];
            a3 += bred[3][w]; a4 += bred[4][w]; a5 += bred[5][w];
        }
        double wgt = diag ? 1.0 : 2.0;   // symmetry: off-diagonal tiles count twice
        atomicAdd(&g_acc[0], wgt * (double)a0);
        atomicAdd(&g_acc[1], wgt * (double)a1);
        atomicAdd(&g_acc[2], wgt * (double)a2);
        atomicAdd(&g_acc[3], wgt * (double)a3);
        if (diag) {
            atomicAdd(&g_acc[4], (double)a4);
            atomicAdd(&g_acc[5], (double)a5);
        }

        __threadfence();
        unsigned prev = atomicAdd(&g_count, 1u);
        if (prev == NBLK - 1) {
            __threadfence();
            double S_dd = g_acc[0], S_oo = g_acc[1], S_do = g_acc[2];
            double a = sqrt(S_dd), b = sqrt(S_oo);
            double ac = fmax(a, 1e-5), bc = fmax(b, 1e-5);
            double q = S_dd / (ac * ac) + S_oo / (bc * bc) - 2.0 * S_do / (ac * bc);
            if (q < 0.0) q = 0.0;
            out[0] = (float)(sqrt(q) + g_acc[3] + g_acc[4] + g_acc[5]);
            // reset state for the next graph replay
            g_acc[0] = 0.0; g_acc[1] = 0.0; g_acc[2] = 0.0;
            g_acc[3] = 0.0; g_acc[4] = 0.0; g_acc[5] = 0.0;
            g_count = 0u;
        }
    }
}

// ---------------------------------------------------------------------------
extern "C" void kernel_launch(void* const* d_in, const int* in_sizes, int n_in,
                              void* d_out, int out_size) {
    const float* cl  = (const float*)d_in[0];  // childrenLower  [4096,32]
    const float* ch  = (const float*)d_in[1];  // childrenHigher [4096,32]
    const float* pL  = (const float*)d_in[2];  // parentL_ [32]
    const float* pH  = (const float*)d_in[3];  // parentH_ [32]
    const float* pR  = (const float*)d_in[4];  // parentRange [32]
    const float* lr  = (const float*)d_in[5];  // leavesRatio [4096]
    const float* om  = (const float*)d_in[6];  // omegaEmb [1024,128]
    const int*  idxs = (const int*)d_in[7];    // idIndexes [1024]
    float* out = (float*)d_out;

    const int SMEM = (4 * TILE * LHS4 + 2 * TILE * WS4) * (int)sizeof(float); // 104448 B
    cudaFuncSetAttribute(pair_kernel, cudaFuncAttributeMaxDynamicSharedMemorySize, SMEM);

    pair_kernel<<<NBLK, dim3(16, 32), SMEM>>>(cl, ch, pL, pH, pR, lr, om, idxs, out);
}

// round 11
// speedup vs baseline: 2.2134x; 1.0013x over previous
#include <cuda_runtime.h>
#include <math.h>

#define NSEL 1024
#define DD 32
#define KK 128
#define EPSF 1e-5f
#define PI_HALF_F 1.57079632679489661923f

#define TILE 64
#define NTB  (NSEL / TILE)            // 16 tiles per side
#define NBLK (NTB * (NTB + 1) / 2)    // 136 triangular blocks (one wave)
#define NTHR 512
#define LHS4 36   // padded row stride for L/H tiles (32 + 4) -> 16B aligned
#define WS4  132  // padded row stride for omega tiles (128 + 4) -> 16B aligned

// ---- global accumulators (zero-initialized at module load; reset each call) ----
__device__ double g_acc[6];     // 0:S_dd 1:S_oo 2:S_do 3:overlap 4:exceed 5:shape
__device__ unsigned g_count;

// ---------------------------------------------------------------------------
__global__ void __launch_bounds__(NTHR)
pair_kernel(const float* __restrict__ cl, const float* __restrict__ ch,
            const float* __restrict__ pL, const float* __restrict__ pH,
            const float* __restrict__ pR, const float* __restrict__ lr,
            const float* __restrict__ om, const int* __restrict__ idxs,
            float* __restrict__ out) {
    extern __shared__ float sm[];
    float* sLi = sm;
    float* sHi = sLi + TILE * LHS4;
    float* sLj = sHi + TILE * LHS4;
    float* sHj = sLj + TILE * LHS4;
    float* sWi = sHj + TILE * LHS4;
    float* sWj = sWi + TILE * WS4;
    __shared__ float sIpI[TILE], sIpJ[TILE];
    __shared__ float bred[6][16];

    int tx = threadIdx.x, ty = threadIdx.y;      // (16, 32)
    int tid = ty * 16 + tx;

    // decode triangular block index -> (by, bx) with by <= bx
    int t = blockIdx.x;
    int by = 0;
    while (t >= NTB - by) { t -= NTB - by; by++; }
    int bx = by + t;
    int i0 = by * TILE;
    int j0 = bx * TILE;
    bool diag = (by == bx);

    // ---- gather L/H tiles (float4 row-chunks) ----
    for (int p = tid; p < TILE * (DD / 4); p += NTHR) {    // 512 slots
        int r = p >> 3, dq = p & 7;
        int gi = idxs[i0 + r];
        int gj = idxs[j0 + r];
        ((float4*)&sLi[r * LHS4])[dq] = ((const float4*)cl)[gi * 8 + dq];
        ((float4*)&sHi[r * LHS4])[dq] = ((const float4*)ch)[gi * 8 + dq];
        ((float4*)&sLj[r * LHS4])[dq] = ((const float4*)cl)[gj * 8 + dq];
        ((float4*)&sHj[r * LHS4])[dq] = ((const float4*)ch)[gj * 8 + dq];
    }
    // ---- omega tiles (coalesced float4) ----
    for (int p = tid; p < TILE * (KK / 4); p += NTHR) {    // 2048 slots
        int r = p >> 5, kq = p & 31;
        ((float4*)&sWi[r * WS4])[kq] = ((const float4*)om)[(i0 + r) * 32 + kq];
        ((float4*)&sWj[r * WS4])[kq] = ((const float4*)om)[(j0 + r) * 32 + kq];
    }
    __syncthreads();

    // ---- per-row ip = sum(w*w): 8 threads per row, 16 floats each ----
    {
        int row = tid >> 3, q = tid & 7;
        const float4* wi = (const float4*)&sWi[row * WS4 + q * 16];
        const float4* wj = (const float4*)&sWj[row * WS4 + q * 16];
        float pi = 0.f, pj = 0.f;
#pragma unroll
        for (int k = 0; k < 4; k++) {
            float4 a = wi[k], b = wj[k];
            pi = fmaf(a.x, a.x, fmaf(a.y, a.y, fmaf(a.z, a.z, fmaf(a.w, a.w, pi))));
            pj = fmaf(b.x, b.x, fmaf(b.y, b.y, fmaf(b.z, b.z, fmaf(b.w, b.w, pj))));
        }
#pragma unroll
        for (int off = 1; off < 8; off <<= 1) {
            pi += __shfl_xor_sync(0xffffffffu, pi, off);
            pj += __shfl_xor_sync(0xffffffffu, pj, off);
        }
        if (q == 0) { sIpI[row] = pi; sIpJ[row] = pj; }
    }

    // ---- exceed + shape: computed once per row-tile, by diagonal blocks ----
    float exc = 0.f, shp = 0.f;
    if (diag) {
        for (int p = tid; p < TILE * DD; p += NTHR) {
            int r = p >> 5, d = p & 31;
            float L = sLi[r * LHS4 + d];
            float H = sHi[r * LHS4 + d];
            float pl = pL[d], ph = pH[d];
            exc += fmaxf(pl - L, 0.f) + fmaxf(H - ph, 0.f)
                 + fmaxf(pl - H, 0.f) + fmaxf(L - ph, 0.f);
            float num = fmaxf((H - L) / pR[d], EPSF);
            float sdiv = num / lr[idxs[i0 + r]];
            sdiv = fminf(fmaxf(sdiv, 0.01f), 1.99f);
            shp += fabsf(tanf((sdiv - 1.0f) * PI_HALF_F));
        }
    }
    __syncthreads();

    // microtile: i-rows {ty, ty+32}, j-cols {tx + 16c, c<4}
    const float* wiBase0 = &sWi[ty * WS4];
    const float* wiBase1 = &sWi[(ty + 32) * WS4];
    const float* wjBase0 = &sWj[tx * WS4];
    const float* wjBase1 = &sWj[(tx + 16) * WS4];
    const float* wjBase2 = &sWj[(tx + 32) * WS4];
    const float* wjBase3 = &sWj[(tx + 48) * WS4];

    float dot[2][4];
#pragma unroll
    for (int r = 0; r < 2; r++)
#pragma unroll
        for (int c = 0; c < 4; c++) dot[r][c] = 0.f;

    // ---- embedding dot products: register double-buffered k-chunks of 4 ----
    {
        float4 wi[2][2], wj[2][4];
        wi[0][0] = *(const float4*)(wiBase0);
        wi[0][1] = *(const float4*)(wiBase1);
        wj[0][0] = *(const float4*)(wjBase0);
        wj[0][1] = *(const float4*)(wjBase1);
        wj[0][2] = *(const float4*)(wjBase2);
        wj[0][3] = *(const float4*)(wjBase3);
#pragma unroll 4
        for (int k = 0; k < KK; k += 4) {
            int cur = (k >> 2) & 1;
            int nxt = cur ^ 1;
            if (k + 4 < KK) {
                wi[nxt][0] = *(const float4*)(wiBase0 + k + 4);
                wi[nxt][1] = *(const float4*)(wiBase1 + k + 4);
                wj[nxt][0] = *(const float4*)(wjBase0 + k + 4);
                wj[nxt][1] = *(const float4*)(wjBase1 + k + 4);
                wj[nxt][2] = *(const float4*)(wjBase2 + k + 4);
                wj[nxt][3] = *(const float4*)(wjBase3 + k + 4);
            }
#pragma unroll
            for (int r = 0; r < 2; r++)
#pragma unroll
                for (int c = 0; c < 4; c++) {
                    float s = fmaf(wi[cur][r].x, wj[cur][c].x, dot[r][c]);
                    s = fmaf(wi[cur][r].y, wj[cur][c].y, s);
                    s = fmaf(wi[cur][r].z, wj[cur][c].z, s);
                    dot[r][c] = fmaf(wi[cur][r].w, wj[cur][c].w, s);
                }
        }
    }

    // ---- box overlap + center distances (d-chunks of 4, unroll 2) ----
    float dacc[2][4], ovacc[2][4];
#pragma unroll
    for (int r = 0; r < 2; r++)
#pragma unroll
        for (int c = 0; c < 4; c++) { dacc[r][c] = 0.f; ovacc[r][c] = 0.f; }

#pragma unroll 2
    for (int d = 0; d < DD; d += 4) {
        float4 Li[2], Hi[2], Si[2], Lj[4], Hj[4], Sj[4];
#pragma unroll
        for (int r = 0; r < 2; r++) {
            Li[r] = *(const float4*)&sLi[(ty + 32 * r) * LHS4 + d];
            Hi[r] = *(const float4*)&sHi[(ty + 32 * r) * LHS4 + d];
            Si[r].x = Li[r].x + Hi[r].x; Si[r].y = Li[r].y + Hi[r].y;
            Si[r].z = Li[r].z + Hi[r].z; Si[r].w = Li[r].w + Hi[r].w;
        }
#pragma unroll
        for (int c = 0; c < 4; c++) {
            Lj[c] = *(const float4*)&sLj[(tx + 16 * c) * LHS4 + d];
            Hj[c] = *(const float4*)&sHj[(tx + 16 * c) * LHS4 + d];
            Sj[c].x = Lj[c].x + Hj[c].x; Sj[c].y = Lj[c].y + Hj[c].y;
            Sj[c].z = Lj[c].z + Hj[c].z; Sj[c].w = Lj[c].w + Hj[c].w;
        }
#pragma unroll
        for (int r = 0; r < 2; r++)
#pragma unroll
            for (int c = 0; c < 4; c++) {
                float u;
                ovacc[r][c] += fmaxf(fminf(Hi[r].x, Hj[c].x) - fmaxf(Li[r].x, Lj[c].x), 0.f);
                u = Si[r].x - Sj[c].x; dacc[r][c] = fmaf(u, u, dacc[r][c]);
                ovacc[r][c] += fmaxf(fminf(Hi[r].y, Hj[c].y) - fmaxf(Li[r].y, Lj[c].y), 0.f);
                u = Si[r].y - Sj[c].y; dacc[r][c] = fmaf(u, u, dacc[r][c]);
                ovacc[r][c] += fmaxf(fminf(Hi[r].z, Hj[c].z) - fmaxf(Li[r].z, Lj[c].z), 0.f);
                u = Si[r].z - Sj[c].z; dacc[r][c] = fmaf(u, u, dacc[r][c]);
                ovacc[r][c] += fmaxf(fminf(Hi[r].w, Hj[c].w) - fmaxf(Li[r].w, Lj[c].w), 0.f);
                u = Si[r].w - Sj[c].w; dacc[r][c] = fmaf(u, u, dacc[r][c]);
            }
    }

    // ---- combine microtile into scalar partials ----
    float ipi[2], ipj[4];
#pragma unroll
    for (int r = 0; r < 2; r++) ipi[r] = sIpI[ty + 32 * r];
#pragma unroll
    for (int c = 0; c < 4; c++) ipj[c] = sIpJ[tx + 16 * c];

    float s_dd = 0.f, s_oo = 0.f, s_do = 0.f, s_ov = 0.f;
#pragma unroll
    for (int r = 0; r < 2; r++)
#pragma unroll
        for (int c = 0; c < 4; c++) {
            float d2v = 0.25f * dacc[r][c];
            float oDv = fmaxf(fmaf(-2.f, dot[r][c], ipi[r] + ipj[c]), EPSF);
            s_dd = fmaf(d2v, d2v, s_dd);
            s_oo = fmaf(oDv, oDv, s_oo);
            s_do = fmaf(d2v, oDv, s_do);
            if ((i0 + ty + 32 * r) != (j0 + tx + 16 * c))
                s_ov += ovacc[r][c];
        }

    // ---- block reduction ----
#pragma unroll
    for (int off = 16; off > 0; off >>= 1) {
        s_dd += __shfl_xor_sync(0xffffffffu, s_dd, off);
        s_oo += __shfl_xor_sync(0xffffffffu, s_oo, off);
        s_do += __shfl_xor_sync(0xffffffffu, s_do, off);
        s_ov += __shfl_xor_sync(0xffffffffu, s_ov, off);
        exc  += __shfl_xor_sync(0xffffffffu, exc,  off);
        shp  += __shfl_xor_sync(0xffffffffu, shp,  off);
    }
    int warp = tid >> 5, lane = tid & 31;
    if (lane == 0) {
        bred[0][warp] = s_dd; bred[1][warp] = s_oo; bred[2][warp] = s_do;
        bred[3][warp] = s_ov; bred[4][warp] = exc;  bred[5][warp] = shp;
    }
    __syncthreads();
    if (tid == 0) {
        float a0 = 0.f, a1 = 0.f, a2 = 0.f, a3 = 0.f, a4 = 0.f, a5 = 0.f;
#pragma unroll
        for (int w = 0; w < 16; w++) {
            a0 += bred[0][w]; a1 += bred[1][w]; a2 += bred[2][w];
            a3 += bred[3][w]; a4 += bred[4][w]; a5 += bred[5][w];
        }
        double wgt = diag ? 1.0 : 2.0;   // symmetry: off-diagonal tiles count twice
        atomicAdd(&g_acc[0], wgt * (double)a0);
        atomicAdd(&g_acc[1], wgt * (double)a1);
        atomicAdd(&g_acc[2], wgt * (double)a2);
        atomicAdd(&g_acc[3], wgt * (double)a3);
        if (diag) {
            atomicAdd(&g_acc[4], (double)a4);
            atomicAdd(&g_acc[5], (double)a5);
        }

        __threadfence();
        unsigned prev = atomicAdd(&g_count, 1u);
        if (prev == NBLK - 1) {
            __threadfence();
            double S_dd = g_acc[0], S_oo = g_acc[1], S_do = g_acc[2];
            double a = sqrt(S_dd), b = sqrt(S_oo);
            double ac = fmax(a, 1e-5), bc = fmax(b, 1e-5);
            double q = S_dd / (ac * ac) + S_oo / (bc * bc) - 2.0 * S_do / (ac * bc);
            if (q < 0.0) q = 0.0;
            out[0] = (float)(sqrt(q) + g_acc[3] + g_acc[4] + g_acc[5]);
            // reset state for the next graph replay
            g_acc[0] = 0.0; g_acc[1] = 0.0; g_acc[2] = 0.0;
            g_acc[3] = 0.0; g_acc[4] = 0.0; g_acc[5] = 0.0;
            g_count = 0u;
        }
    }
}

// ---------------------------------------------------------------------------
extern "C" void kernel_launch(void* const* d_in, const int* in_sizes, int n_in,
                              void* d_out, int out_size) {
    const float* cl  = (const float*)d_in[0];  // childrenLower  [4096,32]
    const float* ch  = (const float*)d_in[1];  // childrenHigher [4096,32]
    const float* pL  = (const float*)d_in[2];  // parentL_ [32]
    const float* pH  = (const float*)d_in[3];  // parentH_ [32]
    const float* pR  = (const float*)d_in[4];  // parentRange [32]
    const float* lr  = (const float*)d_in[5];  // leavesRatio [4096]
    const float* om  = (const float*)d_in[6];  // omegaEmb [1024,128]
    const int*  idxs = (const int*)d_in[7];    // idIndexes [1024]
    float* out = (float*)d_out;

    const int SMEM = (4 * TILE * LHS4 + 2 * TILE * WS4) * (int)sizeof(float); // 104448 B
    cudaFuncSetAttribute(pair_kernel, cudaFuncAttributeMaxDynamicSharedMemorySize, SMEM);

    pair_kernel<<<NBLK, dim3(16, 32), SMEM>>>(cl, ch, pL, pH, pR, lr, om, idxs, out);
}